// round 14
// baseline (speedup 1.0000x reference)
#include <cuda_runtime.h>
#include <cuda_fp16.h>
#include <math.h>

#define NT 512
#define NB 64
#define NI 1024
#define NH 256
#define NG 768   // 3*NH

// ---------------- scratch (device globals: no allocations allowed) ----------
__device__ float    g_gx_f[NT * NB * NG];     // 100.7 MB
__device__ float    g_gx_b[NT * NB * NG];     // 100.7 MB
__device__ unsigned g_srcH[32768 * 512];      // src fp16-hi k-pairs
__device__ unsigned g_wH[1536 * 512];         // Wih_f|Wih_b fp16 hi
__device__ unsigned g_wL[1536 * 512];         // Wih_f|Wih_b fp16 lo (residual)
__device__ unsigned g_woH[256 * 256];         // Wout fp16 hi
__device__ unsigned g_woL[256 * 256];         // Wout fp16 lo
__device__ unsigned g_poutH[32768 * 256];     // h history fp16-hi: [t*64+b][fwd|bwd]
__device__ unsigned g_done[2 * 256];          // gx completion counters per (dir, m-block)

__global__ void init_done_kernel() { g_done[threadIdx.x] = 0u; }

// ---------------- helpers ----------------------------------------------------
__device__ __forceinline__ unsigned hpack(float x, float y) {
    __half2 h2 = __floats2half2_rn(x, y);
    return *reinterpret_cast<unsigned*>(&h2);
}
__device__ __forceinline__ void hsplit(float x, float y, unsigned& hi, unsigned& lo) {
    __half2 h2 = __floats2half2_rn(x, y);
    hi = *reinterpret_cast<unsigned*>(&h2);
    float rx = x - __low2float(h2);
    float ry = y - __high2float(h2);
    __half2 l2 = __floats2half2_rn(rx, ry);
    lo = *reinterpret_cast<unsigned*>(&l2);
}

#define MMA_F16(d, a0, a1, a2, a3, b0, b1)                                      \
    asm volatile("mma.sync.aligned.m16n8k16.row.col.f32.f16.f16.f32 "           \
        "{%0,%1,%2,%3}, {%4,%5,%6,%7}, {%8,%9}, {%0,%1,%2,%3};"                 \
        : "+f"(d[0]), "+f"(d[1]), "+f"(d[2]), "+f"(d[3])                        \
        : "r"(a0), "r"(a1), "r"(a2), "r"(a3), "r"(b0), "r"(b1))

#define MMA_F16A(d, a, b0, b1) MMA_F16(d, (a)[0], (a)[1], (a)[2], (a)[3], b0, b1)

__device__ __forceinline__ void cp16(unsigned smem_dst, const void* gsrc) {
    asm volatile("cp.async.cg.shared.global [%0], [%1], 16;"
                 :: "r"(smem_dst), "l"(gsrc));
}
#define CP_COMMIT() asm volatile("cp.async.commit_group;")
#define CP_WAIT(n)  asm volatile("cp.async.wait_group %0;" :: "n"(n))

__device__ __forceinline__ unsigned smem_u32(const void* p) {
    return (unsigned)__cvta_generic_to_shared(p);
}
__device__ __forceinline__ unsigned mapa_u32(unsigned addr, unsigned rank) {
    unsigned r; asm("mapa.shared::cluster.u32 %0, %1, %2;" : "=r"(r) : "r"(addr), "r"(rank));
    return r;
}
__device__ __forceinline__ void st_async_u32(unsigned raddr, unsigned val, unsigned rmbar) {
    asm volatile("st.async.shared::cluster.mbarrier::complete_tx::bytes.b32 [%0], %1, [%2];"
                 :: "r"(raddr), "r"(val), "r"(rmbar) : "memory");
}
__device__ __forceinline__ void mbar_init(unsigned mbar, unsigned cnt) {
    asm volatile("mbarrier.init.shared.b64 [%0], %1;" :: "r"(mbar), "r"(cnt) : "memory");
}
__device__ __forceinline__ void mbar_arrive_expect(unsigned mbar, unsigned bytes) {
    asm volatile("mbarrier.arrive.expect_tx.shared.b64 _, [%0], %1;"
                 :: "r"(mbar), "r"(bytes) : "memory");
}
__device__ __forceinline__ void mbar_wait(unsigned mbar, unsigned ph) {
    asm volatile(
        "{\n\t.reg .pred P;\n"
        "W%=:\n\t"
        "mbarrier.try_wait.parity.acquire.cluster.shared::cta.b64 P, [%0], %1, 0x989680;\n\t"
        "@P bra.uni D%=;\n\t"
        "bra.uni W%=;\n\t"
        "D%=:\n\t}"
        :: "r"(mbar), "r"(ph) : "memory");
}
#define CLUSTER_SYNC() do {                                                     \
    asm volatile("barrier.cluster.arrive.aligned;" ::: "memory");               \
    asm volatile("barrier.cluster.wait.aligned;" ::: "memory");                 \
} while (0)

__device__ __forceinline__ void wait_done(const unsigned* p) {
    unsigned v;
    asm volatile("ld.acquire.gpu.global.u32 %0, [%1];" : "=r"(v) : "l"(p));
    while (v < 6u) {
        __nanosleep(64);
        asm volatile("ld.acquire.gpu.global.u32 %0, [%1];" : "=r"(v) : "l"(p));
    }
}

// fast transcendentals (rel err ~1e-6)
__device__ __forceinline__ float ex2a(float x) {
    float y; asm("ex2.approx.ftz.f32 %0, %1;" : "=f"(y) : "f"(x)); return y;
}
__device__ __forceinline__ float rcpa(float x) {
    float y; asm("rcp.approx.ftz.f32 %0, %1;" : "=f"(y) : "f"(x)); return y;
}
__device__ __forceinline__ float fsig(float x) {
    return rcpa(1.f + ex2a(-1.4426950408889634f * x));
}
__device__ __forceinline__ float ftanh(float x) {
    return __fmaf_rn(-2.f, rcpa(1.f + ex2a(2.8853900817779268f * x)), 1.f);
}

// ---------------- conversion kernels (run once per launch) ------------------
__global__ __launch_bounds__(256) void conv_src_kernel(const float* __restrict__ a) {
    const int i = blockIdx.x * 256 + threadIdx.x;
    float2 v = ((const float2*)a)[i];
    g_srcH[i] = hpack(v.x, v.y);
}
__global__ __launch_bounds__(256) void conv_wih_kernel(
    const float* __restrict__ f, const float* __restrict__ b) {
    const int i = blockIdx.x * 256 + threadIdx.x;
    float2 v = ((const float2*)f)[i];
    unsigned h, l; hsplit(v.x, v.y, h, l);
    g_wH[i] = h; g_wL[i] = l;
    float2 w = ((const float2*)b)[i];
    hsplit(w.x, w.y, h, l);
    g_wH[768 * 512 + i] = h; g_wL[768 * 512 + i] = l;
}
__global__ __launch_bounds__(256) void conv_wout_kernel(const float* __restrict__ a) {
    const int i = blockIdx.x * 256 + threadIdx.x;
    float2 v = ((const float2*)a)[i];
    unsigned h, l; hsplit(v.x, v.y, h, l);
    g_woH[i] = h; g_woL[i] = l;
}

// ---------------- shared mma tile compute (128x128 tile, 8 warps) -----------
#define SST2 20
#define PB (128 * SST2)     // u32 per plane

__device__ __forceinline__ void mma_tile_f16(
    const unsigned* Ah, const unsigned* Bh, const unsigned* Bl,
    float acc[2][8][4], int wm, int wn, int grp, int tig)
{
#pragma unroll
    for (int kk = 0; kk < 2; kk++) {
        unsigned ah[2][4];
#pragma unroll
        for (int s = 0; s < 2; s++) {
            const int r = wm * 32 + s * 16 + grp;
            const int base = r * SST2 + kk * 8 + tig;
            ah[s][0] = Ah[base];            ah[s][1] = Ah[base + 8 * SST2];
            ah[s][2] = Ah[base + 4];        ah[s][3] = Ah[base + 8 * SST2 + 4];
        }
#pragma unroll
        for (int ns = 0; ns < 8; ns++) {
            const int n = wn * 64 + ns * 8 + grp;
            const int nb = n * SST2 + kk * 8 + tig;
            const unsigned bh0 = Bh[nb], bh1 = Bh[nb + 4];
            const unsigned bl0 = Bl[nb], bl1 = Bl[nb + 4];
#pragma unroll
            for (int s = 0; s < 2; s++) {
                MMA_F16A(acc[s][ns], ah[s], bh0, bh1);
                MMA_F16A(acc[s][ns], ah[s], bl0, bl1);
            }
        }
    }
}

// ---------------- Kernel 1: gx = src @ Wih^T + bih (priority-ordered) -------
// Linear grid 3072. bid = g*12 + i: i<6 -> fwd m-block g (t=2g,2g+1), n-tile i;
// i>=6 -> bwd m-block 255-g, n-tile i-6. Produces gx in exactly the order the
// recurrence consumes it. Signals g_done[dir][mb] on completion.
__global__ __launch_bounds__(256, 2) void gemm_gx_tc(
    const float* __restrict__ bih_f, const float* __restrict__ bih_b)
{
    extern __shared__ unsigned sm[];
    const unsigned sbase = smem_u32(sm);

    const int bid = blockIdx.x;
    const int g = bid / 12, i = bid % 12;
    const bool fwd = (i < 6);
    const int mb = fwd ? g : (255 - g);
    const int m0 = mb * 128;
    const int n0 = (fwd ? i : (i - 6)) * 128;       // column within direction
    const float* bias = fwd ? (bih_f + n0) : (bih_b + n0);
    float* outp = fwd ? g_gx_f : g_gx_b;
    const size_t wrow = (size_t)(fwd ? 0 : NG) * 512;  // weight-plane row offset base

    const int tid = threadIdx.x;
    const int lane = tid & 31, warp = tid >> 5;
    const int wm = warp >> 1, wn = warp & 1;
    const int grp = lane >> 2, tig = lane & 3;
    const int r0 = tid >> 2, c0 = (tid & 3) * 4;

    float acc[2][8][4];
#pragma unroll
    for (int s = 0; s < 2; s++)
#pragma unroll
        for (int ns = 0; ns < 8; ns++)
#pragma unroll
            for (int q = 0; q < 4; q++) acc[s][ns][q] = 0.f;

    auto issue = [&](int kt, int buf) {
        const unsigned b = sbase + (unsigned)buf * 3u * PB * 4u;
#pragma unroll
        for (int l = 0; l < 2; l++) {
            const int row = r0 + l * 64;
            const unsigned d = b + (unsigned)(row * SST2 + c0) * 4u;
            const size_t ga = (size_t)(m0 + row) * 512 + kt * 16 + c0;
            const size_t gb = wrow + (size_t)(n0 + row) * 512 + kt * 16 + c0;
            cp16(d,              g_srcH + ga);
            cp16(d + PB * 4,     g_wH + gb);
            cp16(d + 2 * PB * 4, g_wL + gb);
        }
        CP_COMMIT();
    };

    issue(0, 0);
    issue(1, 1);
    for (int kt = 0; kt < 32; kt++) {
        if (kt == 31) { CP_WAIT(0); } else { CP_WAIT(1); }
        __syncthreads();
        const unsigned* bp = sm + (kt & 1) * 3 * PB;
        mma_tile_f16(bp, bp + PB, bp + 2 * PB, acc, wm, wn, grp, tig);
        __syncthreads();
        if (kt + 2 < 32) issue(kt + 2, kt & 1);
    }

#pragma unroll
    for (int ns = 0; ns < 8; ns++) {
        const int cl = wn * 64 + ns * 8 + tig * 2;
        const float b0 = bias[cl], b1 = bias[cl + 1];
#pragma unroll
        for (int s = 0; s < 2; s++) {
            const int r = m0 + wm * 32 + s * 16 + grp;
            float* p0 = outp + (size_t)r * NG + n0 + cl;
            float* p1 = outp + (size_t)(r + 8) * NG + n0 + cl;
            *(float2*)p0 = make_float2(acc[s][ns][0] + b0, acc[s][ns][1] + b1);
            *(float2*)p1 = make_float2(acc[s][ns][2] + b0, acc[s][ns][3] + b1);
        }
    }

    // completion signal: all threads' stores -> fence -> sync -> counter bump
    __threadfence();
    __syncthreads();
    if (tid == 0) atomicAdd(&g_done[(fwd ? 0 : 256) + mb], 1u);
}

// ---------------- Kernel 2: clustered GRU recurrence (polls gx progress) ----
#define SLOT_U32 1056                 // 8 batches x 132

__global__ __launch_bounds__(384, 1) __cluster_dims__(4, 1, 1)
void gru_rec_clu(
    const float* __restrict__ Whh_f, const float* __restrict__ bhh_f,
    const float* __restrict__ Whh_b, const float* __restrict__ bhh_b)
{
    extern __shared__ unsigned dsm[];
    unsigned* mbar = dsm;                      // 4 x u64
    unsigned* hsH  = dsm + 8;                  // [4][8][132]
    unsigned* wlo  = hsH + 4 * SLOT_U32;       // [192][132]
    float*    red  = (float*)(wlo + 192 * 132);// [192][9]

    const int cta = blockIdx.x;
    const int tid = threadIdx.x;
    const int dir = cta >> 5;
    const int c5  = cta & 31;
    const int group = c5 >> 2;
    const int rank  = c5 & 3;
    const float* Whh = dir ? Whh_b : Whh_f;
    const float* bhh = dir ? bhh_b : bhh_f;
    const float* gx  = dir ? g_gx_b : g_gx_f;
    const unsigned* done = g_done + dir * 256;

    const int lane = tid & 31, w = tid >> 5;   // 12 warps
    const int grp = lane >> 2, tig = lane & 3;
    const int lr0 = 16 * w + grp, lr1 = lr0 + 8;

    unsigned waH[16][4];
    {
        const int g0 = lr0 >> 6, g1 = lr1 >> 6;
        const float* row0 = Whh + (size_t)(g0 * NH + 64 * rank + (lr0 & 63)) * NH;
        const float* row1 = Whh + (size_t)(g1 * NH + 64 * rank + (lr1 & 63)) * NH;
#pragma unroll
        for (int ks = 0; ks < 16; ks++) {
            const int kp0 = ks * 8 + tig, kp1 = kp0 + 4;
            unsigned h, l;
            float2 v;
            v = *(const float2*)(row0 + 2 * kp0); hsplit(v.x, v.y, h, l);
            waH[ks][0] = h; wlo[lr0 * 132 + kp0] = l;
            v = *(const float2*)(row1 + 2 * kp0); hsplit(v.x, v.y, h, l);
            waH[ks][1] = h; wlo[lr1 * 132 + kp0] = l;
            v = *(const float2*)(row0 + 2 * kp1); hsplit(v.x, v.y, h, l);
            waH[ks][2] = h; wlo[lr0 * 132 + kp1] = l;
            v = *(const float2*)(row1 + 2 * kp1); hsplit(v.x, v.y, h, l);
            waH[ks][3] = h; wlo[lr1 * 132 + kp1] = l;
        }
    }

    const int bl = tid >> 5;
    const int jp = lane;
    const int bglob = group * 8 + bl;
    const int jg0 = 64 * rank + 2 * jp;
    float br0 = 0.f, br1 = 0.f, bz0 = 0.f, bz1 = 0.f, bn0 = 0.f, bn1 = 0.f;
    if (tid < 256) {
        br0 = bhh[jg0];       br1 = bhh[jg0 + 1];
        bz0 = bhh[256 + jg0]; bz1 = bhh[256 + jg0 + 1];
        bn0 = bhh[512 + jg0]; bn1 = bhh[512 + jg0 + 1];
    }
    float hp0 = 0.f, hp1 = 0.f;

    for (int i = tid; i < 4 * SLOT_U32; i += 384) hsH[i] = 0u;
    const unsigned mbar_b = smem_u32(mbar);
    if (tid == 0) {
#pragma unroll
        for (int q = 0; q < 4; q++) mbar_init(mbar_b + q * 8, 1);
    }
    __syncthreads();
    CLUSTER_SYNC();

    const unsigned hsH_b = smem_u32(hsH);
    unsigned rH[4], rM[4];
#pragma unroll
    for (int rk = 0; rk < 4; rk++) {
        rH[rk] = mapa_u32(hsH_b, rk);
        rM[rk] = mapa_u32(mbar_b, rk);
    }

    float pxr0, pxr1, pxz0, pxz1, pxn0, pxn1;
    if (tid < 256) {
        const int t0 = dir ? (NT - 1) : 0;
        wait_done(done + (t0 >> 1));
        const float* gp = gx + ((size_t)t0 * NB + bglob) * NG + jg0;
        float2 a = __ldg((const float2*)gp);
        float2 b = __ldg((const float2*)(gp + 256));
        float2 c = __ldg((const float2*)(gp + 512));
        pxr0 = a.x; pxr1 = a.y; pxz0 = b.x; pxz1 = b.y; pxn0 = c.x; pxn1 = c.y;
    }

    unsigned phases = 0;

    for (int s = 0; s < NT; s++) {
        const int rs = s & 3;
        const int ws = (s + 1) & 3;
        const int rb = rs * SLOT_U32;

        if (tid == 0 && s + 1 < NT)
            mbar_arrive_expect(mbar_b + ws * 8, 4096);
        if (s > 0) {
            mbar_wait(mbar_b + rs * 8, (phases >> rs) & 1);
            phases ^= (1u << rs);
        }

        float nxr0 = 0.f, nxr1 = 0.f, nxz0 = 0.f, nxz1 = 0.f, nxn0 = 0.f, nxn1 = 0.f;
        if (tid < 256 && s + 1 < NT) {
            const int tn = dir ? (NT - 2 - s) : (s + 1);
            wait_done(done + (tn >> 1));
            const float* gp = gx + ((size_t)tn * NB + bglob) * NG + jg0;
            float2 a = __ldg((const float2*)gp);
            float2 b = __ldg((const float2*)(gp + 256));
            float2 c = __ldg((const float2*)(gp + 512));
            nxr0 = a.x; nxr1 = a.y; nxz0 = b.x; nxz1 = b.y; nxn0 = c.x; nxn1 = c.y;
        }

        // 2 independent accumulator chains: Wh*h + Wl*h
        float aA[4] = {0.f, 0.f, 0.f, 0.f};
        float aB[4] = {0.f, 0.f, 0.f, 0.f};
#pragma unroll
        for (int ks = 0; ks < 16; ks++) {
            const int kp = ks * 8 + tig;
            const unsigned bh0 = hsH[rb + grp * 132 + kp];
            const unsigned bh1 = hsH[rb + grp * 132 + kp + 4];
            const unsigned al0 = wlo[lr0 * 132 + kp];
            const unsigned al1 = wlo[lr1 * 132 + kp];
            const unsigned al2 = wlo[lr0 * 132 + kp + 4];
            const unsigned al3 = wlo[lr1 * 132 + kp + 4];
            MMA_F16A(aA, waH[ks], bh0, bh1);
            MMA_F16(aB, al0, al1, al2, al3, bh0, bh1);
        }
        red[lr0 * 9 + tig * 2]     = aA[0] + aB[0];
        red[lr0 * 9 + tig * 2 + 1] = aA[1] + aB[1];
        red[lr1 * 9 + tig * 2]     = aA[2] + aB[2];
        red[lr1 * 9 + tig * 2 + 1] = aA[3] + aB[3];
        __syncthreads();

        if (tid < 256) {
            const int j0 = 2 * jp, j1 = j0 + 1;
            const float ghr0 = red[j0 * 9 + bl],         ghr1 = red[j1 * 9 + bl];
            const float ghz0 = red[(64 + j0) * 9 + bl],  ghz1 = red[(64 + j1) * 9 + bl];
            const float ghn0 = red[(128 + j0) * 9 + bl], ghn1 = red[(128 + j1) * 9 + bl];

            const float r0 = fsig(pxr0 + ghr0 + br0);
            const float z0 = fsig(pxz0 + ghz0 + bz0);
            const float n0 = ftanh(pxn0 + r0 * (ghn0 + bn0));
            const float h0 = (1.f - z0) * n0 + z0 * hp0;
            const float r1 = fsig(pxr1 + ghr1 + br1);
            const float z1 = fsig(pxz1 + ghz1 + bz1);
            const float n1 = ftanh(pxn1 + r1 * (ghn1 + bn1));
            const float h1 = (1.f - z1) * n1 + z1 * hp1;
            hp0 = h0; hp1 = h1;

            const unsigned hi = hpack(h0, h1);
            const int t = dir ? (NT - 1 - s) : s;
            const int col = rank * 32 + jp;
            if (s + 1 < NT) {
                const unsigned offH = (unsigned)(ws * SLOT_U32 + bl * 132 + col) * 4u;
                const unsigned mb_off = (unsigned)(ws * 8);
#pragma unroll
                for (int rk = 0; rk < 4; rk++)
                    st_async_u32(rH[rk] + offH, hi, rM[rk] + mb_off);
            }
            g_poutH[((size_t)t * NB + bglob) * 256 + dir * 128 + col] = hi;

            pxr0 = nxr0; pxr1 = nxr1; pxz0 = nxz0; pxz1 = nxz1; pxn0 = nxn0; pxn1 = nxn1;
        }
    }
}

// ---------------- Kernel 3: outputs = h_hist @ Wout^T + bout ----------------
__global__ __launch_bounds__(256, 2) void gemm_proj_tc(
    const float* __restrict__ bout, float* __restrict__ dst)
{
    extern __shared__ unsigned sm[];
    const unsigned sbase = smem_u32(sm);

    const int m0 = blockIdx.x * 128;
    const int n0 = blockIdx.y * 128;
    const int tid = threadIdx.x;
    const int lane = tid & 31, warp = tid >> 5;
    const int wm = warp >> 1, wn = warp & 1;
    const int grp = lane >> 2, tig = lane & 3;
    const int r0 = tid >> 2, c0 = (tid & 3) * 4;

    float acc[2][8][4];
#pragma unroll
    for (int s = 0; s < 2; s++)
#pragma unroll
        for (int ns = 0; ns < 8; ns++)
#pragma unroll
            for (int q = 0; q < 4; q++) acc[s][ns][q] = 0.f;

    auto issue = [&](int kt, int buf) {
        const unsigned b = sbase + (unsigned)buf * 3u * PB * 4u;
#pragma unroll
        for (int l = 0; l < 2; l++) {
            const int row = r0 + l * 64;
            const unsigned d = b + (unsigned)(row * SST2 + c0) * 4u;
            const size_t ga = (size_t)(m0 + row) * 256 + kt * 16 + c0;
            const size_t gb = (size_t)(n0 + row) * 256 + kt * 16 + c0;
            cp16(d,              g_poutH + ga);
            cp16(d + PB * 4,     g_woH + gb);
            cp16(d + 2 * PB * 4, g_woL + gb);
        }
        CP_COMMIT();
    };

    issue(0, 0);
    issue(1, 1);
    for (int kt = 0; kt < 16; kt++) {
        if (kt == 15) { CP_WAIT(0); } else { CP_WAIT(1); }
        __syncthreads();
        const unsigned* bp = sm + (kt & 1) * 3 * PB;
        mma_tile_f16(bp, bp + PB, bp + 2 * PB, acc, wm, wn, grp, tig);
        __syncthreads();
        if (kt + 2 < 16) issue(kt + 2, kt & 1);
    }

#pragma unroll
    for (int ns = 0; ns < 8; ns++) {
        const int cl = wn * 64 + ns * 8 + tig * 2;
        const float b0 = bout[n0 + cl], b1 = bout[n0 + cl + 1];
#pragma unroll
        for (int s = 0; s < 2; s++) {
            const int r = m0 + wm * 32 + s * 16 + grp;
            float* p0 = dst + (size_t)r * NH + n0 + cl;
            float* p1 = dst + (size_t)(r + 8) * NH + n0 + cl;
            *(float2*)p0 = make_float2(acc[s][ns][0] + b0, acc[s][ns][1] + b1);
            *(float2*)p1 = make_float2(acc[s][ns][2] + b0, acc[s][ns][3] + b1);
        }
    }
}

// ---------------- Kernel 4: hidden = tanh([h_f|h_b] @ Whid^T + bhid) --------
__global__ __launch_bounds__(256) void hidden_kernel(
    const float* __restrict__ Whid, const float* __restrict__ bhid,
    float* __restrict__ outh)
{
    __shared__ float hc[512];
    const int b = blockIdx.x, tid = threadIdx.x;
    const size_t row = (tid < 128) ? ((size_t)(NT - 1) * NB + b) : (size_t)b;
    const unsigned hH = g_poutH[row * 256 + tid];
    __half2 h2 = *reinterpret_cast<const __half2*>(&hH);
    hc[2 * tid]     = __low2float(h2);
    hc[2 * tid + 1] = __high2float(h2);
    __syncthreads();
    const float* w = Whid + (size_t)tid * 512;
    float ssum = bhid[tid];
#pragma unroll 8
    for (int k = 0; k < 512; k++) ssum += hc[k] * w[k];
    outh[(size_t)b * NH + tid] = tanhf(ssum);
}

// ---------------- launcher ---------------------------------------------------
extern "C" void kernel_launch(void* const* d_in, const int* in_sizes, int n_in,
                              void* d_out, int out_size)
{
    const float* src   = (const float*)d_in[0];
    const float* Wih_f = (const float*)d_in[1];
    const float* Whh_f = (const float*)d_in[2];
    const float* bih_f = (const float*)d_in[3];
    const float* bhh_f = (const float*)d_in[4];
    const float* Wih_b = (const float*)d_in[5];
    const float* Whh_b = (const float*)d_in[6];
    const float* bih_b = (const float*)d_in[7];
    const float* bhh_b = (const float*)d_in[8];
    const float* Wout  = (const float*)d_in[9];
    const float* bout  = (const float*)d_in[10];
    const float* Whid  = (const float*)d_in[11];
    const float* bhid  = (const float*)d_in[12];
    float* out = (float*)d_out;

    const int gemm_smem = 2 * 3 * PB * (int)sizeof(unsigned);   // 61440
    cudaFuncSetAttribute(gemm_gx_tc,
                         cudaFuncAttributeMaxDynamicSharedMemorySize, gemm_smem);
    cudaFuncSetAttribute(gemm_proj_tc,
                         cudaFuncAttributeMaxDynamicSharedMemorySize, gemm_smem);
    const int rec_smem = (8 + 4 * SLOT_U32 + 192 * 132) * (int)sizeof(unsigned)
                       + 192 * 9 * (int)sizeof(float) + 64;     // ~126 KB
    cudaFuncSetAttribute(gru_rec_clu,
                         cudaFuncAttributeMaxDynamicSharedMemorySize, rec_smem);

    // fork/join streams (created fresh each call; capture-safe event pattern)
    cudaStream_t s2;
    cudaStreamCreate(&s2);
    cudaEvent_t evF, evJ;
    cudaEventCreateWithFlags(&evF, cudaEventDisableTiming);
    cudaEventCreateWithFlags(&evJ, cudaEventDisableTiming);

    init_done_kernel<<<1, 512>>>();
    conv_src_kernel<<<65536, 256>>>(src);
    conv_wih_kernel<<<1536, 256>>>(Wih_f, Wih_b);
    conv_wout_kernel<<<256, 256>>>(Wout);

    cudaEventRecord(evF, 0);
    cudaStreamWaitEvent(s2, evF, 0);

    gemm_gx_tc<<<3072, 256, gemm_smem>>>(bih_f, bih_b);                 // stream 0
    gru_rec_clu<<<64, 384, rec_smem, s2>>>(Whh_f, bhh_f, Whh_b, bhh_b); // stream 2

    cudaEventRecord(evJ, s2);
    cudaStreamWaitEvent(0, evJ, 0);

    gemm_proj_tc<<<dim3(256, 2), 256, gemm_smem>>>(bout, out);
    hidden_kernel<<<64, 256>>>(Whid, bhid, out + (size_t)NT * NB * NH);
}

// round 16
// speedup vs baseline: 1.1398x; 1.1398x over previous
#include <cuda_runtime.h>
#include <cuda_fp16.h>
#include <math.h>

#define NT 512
#define NB 64
#define NI 1024
#define NH 256
#define NG 768   // 3*NH

// ---------------- scratch (device globals: no allocations allowed) ----------
__device__ float    g_gx_f[NT * NB * NG];     // 100.7 MB
__device__ float    g_gx_b[NT * NB * NG];     // 100.7 MB
__device__ unsigned g_srcH[32768 * 512];      // src fp16-hi k-pairs
__device__ unsigned g_wH[1536 * 512];         // Wih_f|Wih_b fp16 hi
__device__ unsigned g_wL[1536 * 512];         // Wih_f|Wih_b fp16 lo (residual)
__device__ unsigned g_woH[256 * 256];         // Wout fp16 hi
__device__ unsigned g_woL[256 * 256];         // Wout fp16 lo
__device__ unsigned g_poutH[32768 * 256];     // h history fp16-hi: [t*64+b][fwd|bwd]
__device__ unsigned g_done[2 * 256];          // gx completion counters per (dir, m-block)

__global__ void init_done_kernel() { g_done[threadIdx.x] = 0u; }

// ---------------- helpers ----------------------------------------------------
__device__ __forceinline__ unsigned hpack(float x, float y) {
    __half2 h2 = __floats2half2_rn(x, y);
    return *reinterpret_cast<unsigned*>(&h2);
}
__device__ __forceinline__ void hsplit(float x, float y, unsigned& hi, unsigned& lo) {
    __half2 h2 = __floats2half2_rn(x, y);
    hi = *reinterpret_cast<unsigned*>(&h2);
    float rx = x - __low2float(h2);
    float ry = y - __high2float(h2);
    __half2 l2 = __floats2half2_rn(rx, ry);
    lo = *reinterpret_cast<unsigned*>(&l2);
}

#define MMA_F16(d, a0, a1, a2, a3, b0, b1)                                      \
    asm volatile("mma.sync.aligned.m16n8k16.row.col.f32.f16.f16.f32 "           \
        "{%0,%1,%2,%3}, {%4,%5,%6,%7}, {%8,%9}, {%0,%1,%2,%3};"                 \
        : "+f"(d[0]), "+f"(d[1]), "+f"(d[2]), "+f"(d[3])                        \
        : "r"(a0), "r"(a1), "r"(a2), "r"(a3), "r"(b0), "r"(b1))

#define MMA_F16A(d, a, b0, b1) MMA_F16(d, (a)[0], (a)[1], (a)[2], (a)[3], b0, b1)

__device__ __forceinline__ void cp16(unsigned smem_dst, const void* gsrc) {
    asm volatile("cp.async.cg.shared.global [%0], [%1], 16;"
                 :: "r"(smem_dst), "l"(gsrc));
}
#define CP_COMMIT() asm volatile("cp.async.commit_group;")
#define CP_WAIT(n)  asm volatile("cp.async.wait_group %0;" :: "n"(n))

__device__ __forceinline__ unsigned smem_u32(const void* p) {
    return (unsigned)__cvta_generic_to_shared(p);
}
__device__ __forceinline__ unsigned mapa_u32(unsigned addr, unsigned rank) {
    unsigned r; asm("mapa.shared::cluster.u32 %0, %1, %2;" : "=r"(r) : "r"(addr), "r"(rank));
    return r;
}
__device__ __forceinline__ void st_async_u32(unsigned raddr, unsigned val, unsigned rmbar) {
    asm volatile("st.async.shared::cluster.mbarrier::complete_tx::bytes.b32 [%0], %1, [%2];"
                 :: "r"(raddr), "r"(val), "r"(rmbar) : "memory");
}
__device__ __forceinline__ void mbar_init(unsigned mbar, unsigned cnt) {
    asm volatile("mbarrier.init.shared.b64 [%0], %1;" :: "r"(mbar), "r"(cnt) : "memory");
}
__device__ __forceinline__ void mbar_arrive_expect(unsigned mbar, unsigned bytes) {
    asm volatile("mbarrier.arrive.expect_tx.shared.b64 _, [%0], %1;"
                 :: "r"(mbar), "r"(bytes) : "memory");
}
__device__ __forceinline__ void mbar_wait(unsigned mbar, unsigned ph) {
    asm volatile(
        "{\n\t.reg .pred P;\n"
        "W%=:\n\t"
        "mbarrier.try_wait.parity.acquire.cluster.shared::cta.b64 P, [%0], %1, 0x989680;\n\t"
        "@P bra.uni D%=;\n\t"
        "bra.uni W%=;\n\t"
        "D%=:\n\t}"
        :: "r"(mbar), "r"(ph) : "memory");
}
#define CLUSTER_SYNC() do {                                                     \
    asm volatile("barrier.cluster.arrive.aligned;" ::: "memory");               \
    asm volatile("barrier.cluster.wait.aligned;" ::: "memory");                 \
} while (0)

__device__ __forceinline__ void wait_done(const unsigned* p) {
    unsigned v;
    asm volatile("ld.acquire.gpu.global.u32 %0, [%1];" : "=r"(v) : "l"(p));
    while (v < 6u) {
        __nanosleep(64);
        asm volatile("ld.acquire.gpu.global.u32 %0, [%1];" : "=r"(v) : "l"(p));
    }
}

// COHERENT L2 load (the __ldg/nc path is outside the consistency model and
// raced with the concurrent producer in R15).
__device__ __forceinline__ float2 ldcg2(const float* p) {
    float2 v;
    asm volatile("ld.global.cg.v2.f32 {%0,%1}, [%2];"
                 : "=f"(v.x), "=f"(v.y) : "l"(p));
    return v;
}

// fast transcendentals (rel err ~1e-6)
__device__ __forceinline__ float ex2a(float x) {
    float y; asm("ex2.approx.ftz.f32 %0, %1;" : "=f"(y) : "f"(x)); return y;
}
__device__ __forceinline__ float rcpa(float x) {
    float y; asm("rcp.approx.ftz.f32 %0, %1;" : "=f"(y) : "f"(x)); return y;
}
__device__ __forceinline__ float fsig(float x) {
    return rcpa(1.f + ex2a(-1.4426950408889634f * x));
}
__device__ __forceinline__ float ftanh(float x) {
    return __fmaf_rn(-2.f, rcpa(1.f + ex2a(2.8853900817779268f * x)), 1.f);
}

// ---------------- conversion kernels (run once per launch) ------------------
__global__ __launch_bounds__(256) void conv_src_kernel(const float* __restrict__ a) {
    const int i = blockIdx.x * 256 + threadIdx.x;
    float2 v = ((const float2*)a)[i];
    g_srcH[i] = hpack(v.x, v.y);
}
__global__ __launch_bounds__(256) void conv_wih_kernel(
    const float* __restrict__ f, const float* __restrict__ b) {
    const int i = blockIdx.x * 256 + threadIdx.x;
    float2 v = ((const float2*)f)[i];
    unsigned h, l; hsplit(v.x, v.y, h, l);
    g_wH[i] = h; g_wL[i] = l;
    float2 w = ((const float2*)b)[i];
    hsplit(w.x, w.y, h, l);
    g_wH[768 * 512 + i] = h; g_wL[768 * 512 + i] = l;
}
__global__ __launch_bounds__(256) void conv_wout_kernel(const float* __restrict__ a) {
    const int i = blockIdx.x * 256 + threadIdx.x;
    float2 v = ((const float2*)a)[i];
    unsigned h, l; hsplit(v.x, v.y, h, l);
    g_woH[i] = h; g_woL[i] = l;
}

// ---------------- shared mma tile compute (128x128 tile, 8 warps) -----------
#define SST2 20
#define PB (128 * SST2)     // u32 per plane

__device__ __forceinline__ void mma_tile_f16(
    const unsigned* Ah, const unsigned* Bh, const unsigned* Bl,
    float acc[2][8][4], int wm, int wn, int grp, int tig)
{
#pragma unroll
    for (int kk = 0; kk < 2; kk++) {
        unsigned ah[2][4];
#pragma unroll
        for (int s = 0; s < 2; s++) {
            const int r = wm * 32 + s * 16 + grp;
            const int base = r * SST2 + kk * 8 + tig;
            ah[s][0] = Ah[base];            ah[s][1] = Ah[base + 8 * SST2];
            ah[s][2] = Ah[base + 4];        ah[s][3] = Ah[base + 8 * SST2 + 4];
        }
#pragma unroll
        for (int ns = 0; ns < 8; ns++) {
            const int n = wn * 64 + ns * 8 + grp;
            const int nb = n * SST2 + kk * 8 + tig;
            const unsigned bh0 = Bh[nb], bh1 = Bh[nb + 4];
            const unsigned bl0 = Bl[nb], bl1 = Bl[nb + 4];
#pragma unroll
            for (int s = 0; s < 2; s++) {
                MMA_F16A(acc[s][ns], ah[s], bh0, bh1);
                MMA_F16A(acc[s][ns], ah[s], bl0, bl1);
            }
        }
    }
}

// ---------------- Kernel 1: gx = src @ Wih^T + bih (priority-ordered) -------
// Linear grid 3072. bid = g*12 + i: i<6 -> fwd m-block g (t=2g,2g+1), n-tile i;
// i>=6 -> bwd m-block 255-g, n-tile i-6. Signals g_done[dir][mb] on completion
// with RELEASE semantics (pairs with consumer's acquire poll).
__global__ __launch_bounds__(256, 2) void gemm_gx_tc(
    const float* __restrict__ bih_f, const float* __restrict__ bih_b)
{
    extern __shared__ unsigned sm[];
    const unsigned sbase = smem_u32(sm);

    const int bid = blockIdx.x;
    const int g = bid / 12, i = bid % 12;
    const bool fwd = (i < 6);
    const int mb = fwd ? g : (255 - g);
    const int m0 = mb * 128;
    const int n0 = (fwd ? i : (i - 6)) * 128;
    const float* bias = fwd ? (bih_f + n0) : (bih_b + n0);
    float* outp = fwd ? g_gx_f : g_gx_b;
    const size_t wrow = (size_t)(fwd ? 0 : NG) * 512;

    const int tid = threadIdx.x;
    const int lane = tid & 31, warp = tid >> 5;
    const int wm = warp >> 1, wn = warp & 1;
    const int grp = lane >> 2, tig = lane & 3;
    const int r0 = tid >> 2, c0 = (tid & 3) * 4;

    float acc[2][8][4];
#pragma unroll
    for (int s = 0; s < 2; s++)
#pragma unroll
        for (int ns = 0; ns < 8; ns++)
#pragma unroll
            for (int q = 0; q < 4; q++) acc[s][ns][q] = 0.f;

    auto issue = [&](int kt, int buf) {
        const unsigned b = sbase + (unsigned)buf * 3u * PB * 4u;
#pragma unroll
        for (int l = 0; l < 2; l++) {
            const int row = r0 + l * 64;
            const unsigned d = b + (unsigned)(row * SST2 + c0) * 4u;
            const size_t ga = (size_t)(m0 + row) * 512 + kt * 16 + c0;
            const size_t gb = wrow + (size_t)(n0 + row) * 512 + kt * 16 + c0;
            cp16(d,              g_srcH + ga);
            cp16(d + PB * 4,     g_wH + gb);
            cp16(d + 2 * PB * 4, g_wL + gb);
        }
        CP_COMMIT();
    };

    issue(0, 0);
    issue(1, 1);
    for (int kt = 0; kt < 32; kt++) {
        if (kt == 31) { CP_WAIT(0); } else { CP_WAIT(1); }
        __syncthreads();
        const unsigned* bp = sm + (kt & 1) * 3 * PB;
        mma_tile_f16(bp, bp + PB, bp + 2 * PB, acc, wm, wn, grp, tig);
        __syncthreads();
        if (kt + 2 < 32) issue(kt + 2, kt & 1);
    }

#pragma unroll
    for (int ns = 0; ns < 8; ns++) {
        const int cl = wn * 64 + ns * 8 + tig * 2;
        const float b0 = bias[cl], b1 = bias[cl + 1];
#pragma unroll
        for (int s = 0; s < 2; s++) {
            const int r = m0 + wm * 32 + s * 16 + grp;
            float* p0 = outp + (size_t)r * NG + n0 + cl;
            float* p1 = outp + (size_t)(r + 8) * NG + n0 + cl;
            *(float2*)p0 = make_float2(acc[s][ns][0] + b0, acc[s][ns][1] + b1);
            *(float2*)p1 = make_float2(acc[s][ns][2] + b0, acc[s][ns][3] + b1);
        }
    }

    __threadfence();
    __syncthreads();
    if (tid == 0) {
        unsigned* cp = &g_done[(fwd ? 0 : 256) + mb];
        asm volatile("red.release.gpu.global.add.u32 [%0], %1;"
                     :: "l"(cp), "r"(1u) : "memory");
    }
}

// ---------------- Kernel 2: clustered GRU recurrence (polls gx progress) ----
#define SLOT_U32 1056                 // 8 batches x 132

__global__ __launch_bounds__(384, 1) __cluster_dims__(4, 1, 1)
void gru_rec_clu(
    const float* __restrict__ Whh_f, const float* __restrict__ bhh_f,
    const float* __restrict__ Whh_b, const float* __restrict__ bhh_b)
{
    extern __shared__ unsigned dsm[];
    unsigned* mbar = dsm;                      // 4 x u64
    unsigned* hsH  = dsm + 8;                  // [4][8][132]
    unsigned* wlo  = hsH + 4 * SLOT_U32;       // [192][132]
    float*    red  = (float*)(wlo + 192 * 132);// [192][9]

    const int cta = blockIdx.x;
    const int tid = threadIdx.x;
    const int dir = cta >> 5;
    const int c5  = cta & 31;
    const int group = c5 >> 2;
    const int rank  = c5 & 3;
    const float* Whh = dir ? Whh_b : Whh_f;
    const float* bhh = dir ? bhh_b : bhh_f;
    const float* gx  = dir ? g_gx_b : g_gx_f;
    const unsigned* done = g_done + dir * 256;

    const int lane = tid & 31, w = tid >> 5;   // 12 warps
    const int grp = lane >> 2, tig = lane & 3;
    const int lr0 = 16 * w + grp, lr1 = lr0 + 8;

    unsigned waH[16][4];
    {
        const int g0 = lr0 >> 6, g1 = lr1 >> 6;
        const float* row0 = Whh + (size_t)(g0 * NH + 64 * rank + (lr0 & 63)) * NH;
        const float* row1 = Whh + (size_t)(g1 * NH + 64 * rank + (lr1 & 63)) * NH;
#pragma unroll
        for (int ks = 0; ks < 16; ks++) {
            const int kp0 = ks * 8 + tig, kp1 = kp0 + 4;
            unsigned h, l;
            float2 v;
            v = *(const float2*)(row0 + 2 * kp0); hsplit(v.x, v.y, h, l);
            waH[ks][0] = h; wlo[lr0 * 132 + kp0] = l;
            v = *(const float2*)(row1 + 2 * kp0); hsplit(v.x, v.y, h, l);
            waH[ks][1] = h; wlo[lr1 * 132 + kp0] = l;
            v = *(const float2*)(row0 + 2 * kp1); hsplit(v.x, v.y, h, l);
            waH[ks][2] = h; wlo[lr0 * 132 + kp1] = l;
            v = *(const float2*)(row1 + 2 * kp1); hsplit(v.x, v.y, h, l);
            waH[ks][3] = h; wlo[lr1 * 132 + kp1] = l;
        }
    }

    const int bl = tid >> 5;
    const int jp = lane;
    const int bglob = group * 8 + bl;
    const int jg0 = 64 * rank + 2 * jp;
    float br0 = 0.f, br1 = 0.f, bz0 = 0.f, bz1 = 0.f, bn0 = 0.f, bn1 = 0.f;
    if (tid < 256) {
        br0 = bhh[jg0];       br1 = bhh[jg0 + 1];
        bz0 = bhh[256 + jg0]; bz1 = bhh[256 + jg0 + 1];
        bn0 = bhh[512 + jg0]; bn1 = bhh[512 + jg0 + 1];
    }
    float hp0 = 0.f, hp1 = 0.f;

    for (int i = tid; i < 4 * SLOT_U32; i += 384) hsH[i] = 0u;
    const unsigned mbar_b = smem_u32(mbar);
    if (tid == 0) {
#pragma unroll
        for (int q = 0; q < 4; q++) mbar_init(mbar_b + q * 8, 1);
    }
    __syncthreads();
    CLUSTER_SYNC();

    const unsigned hsH_b = smem_u32(hsH);
    unsigned rH[4], rM[4];
#pragma unroll
    for (int rk = 0; rk < 4; rk++) {
        rH[rk] = mapa_u32(hsH_b, rk);
        rM[rk] = mapa_u32(mbar_b, rk);
    }

    float pxr0, pxr1, pxz0, pxz1, pxn0, pxn1;
    if (tid < 256) {
        const int t0 = dir ? (NT - 1) : 0;
        wait_done(done + (t0 >> 1));
        const float* gp = gx + ((size_t)t0 * NB + bglob) * NG + jg0;
        float2 a = ldcg2(gp);
        float2 b = ldcg2(gp + 256);
        float2 c = ldcg2(gp + 512);
        pxr0 = a.x; pxr1 = a.y; pxz0 = b.x; pxz1 = b.y; pxn0 = c.x; pxn1 = c.y;
    }

    unsigned phases = 0;

    for (int s = 0; s < NT; s++) {
        const int rs = s & 3;
        const int ws = (s + 1) & 3;
        const int rb = rs * SLOT_U32;

        if (tid == 0 && s + 1 < NT)
            mbar_arrive_expect(mbar_b + ws * 8, 4096);
        if (s > 0) {
            mbar_wait(mbar_b + rs * 8, (phases >> rs) & 1);
            phases ^= (1u << rs);
        }

        float nxr0 = 0.f, nxr1 = 0.f, nxz0 = 0.f, nxz1 = 0.f, nxn0 = 0.f, nxn1 = 0.f;
        if (tid < 256 && s + 1 < NT) {
            const int tn = dir ? (NT - 2 - s) : (s + 1);
            wait_done(done + (tn >> 1));
            const float* gp = gx + ((size_t)tn * NB + bglob) * NG + jg0;
            float2 a = ldcg2(gp);
            float2 b = ldcg2(gp + 256);
            float2 c = ldcg2(gp + 512);
            nxr0 = a.x; nxr1 = a.y; nxz0 = b.x; nxz1 = b.y; nxn0 = c.x; nxn1 = c.y;
        }

        float aA[4] = {0.f, 0.f, 0.f, 0.f};
        float aB[4] = {0.f, 0.f, 0.f, 0.f};
#pragma unroll
        for (int ks = 0; ks < 16; ks++) {
            const int kp = ks * 8 + tig;
            const unsigned bh0 = hsH[rb + grp * 132 + kp];
            const unsigned bh1 = hsH[rb + grp * 132 + kp + 4];
            const unsigned al0 = wlo[lr0 * 132 + kp];
            const unsigned al1 = wlo[lr1 * 132 + kp];
            const unsigned al2 = wlo[lr0 * 132 + kp + 4];
            const unsigned al3 = wlo[lr1 * 132 + kp + 4];
            MMA_F16A(aA, waH[ks], bh0, bh1);
            MMA_F16(aB, al0, al1, al2, al3, bh0, bh1);
        }
        red[lr0 * 9 + tig * 2]     = aA[0] + aB[0];
        red[lr0 * 9 + tig * 2 + 1] = aA[1] + aB[1];
        red[lr1 * 9 + tig * 2]     = aA[2] + aB[2];
        red[lr1 * 9 + tig * 2 + 1] = aA[3] + aB[3];
        __syncthreads();

        if (tid < 256) {
            const int j0 = 2 * jp, j1 = j0 + 1;
            const float ghr0 = red[j0 * 9 + bl],         ghr1 = red[j1 * 9 + bl];
            const float ghz0 = red[(64 + j0) * 9 + bl],  ghz1 = red[(64 + j1) * 9 + bl];
            const float ghn0 = red[(128 + j0) * 9 + bl], ghn1 = red[(128 + j1) * 9 + bl];

            const float r0 = fsig(pxr0 + ghr0 + br0);
            const float z0 = fsig(pxz0 + ghz0 + bz0);
            const float n0 = ftanh(pxn0 + r0 * (ghn0 + bn0));
            const float h0 = (1.f - z0) * n0 + z0 * hp0;
            const float r1 = fsig(pxr1 + ghr1 + br1);
            const float z1 = fsig(pxz1 + ghz1 + bz1);
            const float n1 = ftanh(pxn1 + r1 * (ghn1 + bn1));
            const float h1 = (1.f - z1) * n1 + z1 * hp1;
            hp0 = h0; hp1 = h1;

            const unsigned hi = hpack(h0, h1);
            const int t = dir ? (NT - 1 - s) : s;
            const int col = rank * 32 + jp;
            if (s + 1 < NT) {
                const unsigned offH = (unsigned)(ws * SLOT_U32 + bl * 132 + col) * 4u;
                const unsigned mb_off = (unsigned)(ws * 8);
#pragma unroll
                for (int rk = 0; rk < 4; rk++)
                    st_async_u32(rH[rk] + offH, hi, rM[rk] + mb_off);
            }
            g_poutH[((size_t)t * NB + bglob) * 256 + dir * 128 + col] = hi;

            pxr0 = nxr0; pxr1 = nxr1; pxz0 = nxz0; pxz1 = nxz1; pxn0 = nxn0; pxn1 = nxn1;
        }
    }
}

// ---------------- Kernel 3: outputs = h_hist @ Wout^T + bout ----------------
__global__ __launch_bounds__(256, 2) void gemm_proj_tc(
    const float* __restrict__ bout, float* __restrict__ dst)
{
    extern __shared__ unsigned sm[];
    const unsigned sbase = smem_u32(sm);

    const int m0 = blockIdx.x * 128;
    const int n0 = blockIdx.y * 128;
    const int tid = threadIdx.x;
    const int lane = tid & 31, warp = tid >> 5;
    const int wm = warp >> 1, wn = warp & 1;
    const int grp = lane >> 2, tig = lane & 3;
    const int r0 = tid >> 2, c0 = (tid & 3) * 4;

    float acc[2][8][4];
#pragma unroll
    for (int s = 0; s < 2; s++)
#pragma unroll
        for (int ns = 0; ns < 8; ns++)
#pragma unroll
            for (int q = 0; q < 4; q++) acc[s][ns][q] = 0.f;

    auto issue = [&](int kt, int buf) {
        const unsigned b = sbase + (unsigned)buf * 3u * PB * 4u;
#pragma unroll
        for (int l = 0; l < 2; l++) {
            const int row = r0 + l * 64;
            const unsigned d = b + (unsigned)(row * SST2 + c0) * 4u;
            const size_t ga = (size_t)(m0 + row) * 256 + kt * 16 + c0;
            const size_t gb = (size_t)(n0 + row) * 256 + kt * 16 + c0;
            cp16(d,              g_poutH + ga);
            cp16(d + PB * 4,     g_woH + gb);
            cp16(d + 2 * PB * 4, g_woL + gb);
        }
        CP_COMMIT();
    };

    issue(0, 0);
    issue(1, 1);
    for (int kt = 0; kt < 16; kt++) {
        if (kt == 15) { CP_WAIT(0); } else { CP_WAIT(1); }
        __syncthreads();
        const unsigned* bp = sm + (kt & 1) * 3 * PB;
        mma_tile_f16(bp, bp + PB, bp + 2 * PB, acc, wm, wn, grp, tig);
        __syncthreads();
        if (kt + 2 < 16) issue(kt + 2, kt & 1);
    }

#pragma unroll
    for (int ns = 0; ns < 8; ns++) {
        const int cl = wn * 64 + ns * 8 + tig * 2;
        const float b0 = bout[n0 + cl], b1 = bout[n0 + cl + 1];
#pragma unroll
        for (int s = 0; s < 2; s++) {
            const int r = m0 + wm * 32 + s * 16 + grp;
            float* p0 = dst + (size_t)r * NH + n0 + cl;
            float* p1 = dst + (size_t)(r + 8) * NH + n0 + cl;
            *(float2*)p0 = make_float2(acc[s][ns][0] + b0, acc[s][ns][1] + b1);
            *(float2*)p1 = make_float2(acc[s][ns][2] + b0, acc[s][ns][3] + b1);
        }
    }
}

// ---------------- Kernel 4: hidden = tanh([h_f|h_b] @ Whid^T + bhid) --------
__global__ __launch_bounds__(256) void hidden_kernel(
    const float* __restrict__ Whid, const float* __restrict__ bhid,
    float* __restrict__ outh)
{
    __shared__ float hc[512];
    const int b = blockIdx.x, tid = threadIdx.x;
    const size_t row = (tid < 128) ? ((size_t)(NT - 1) * NB + b) : (size_t)b;
    const unsigned hH = g_poutH[row * 256 + tid];
    __half2 h2 = *reinterpret_cast<const __half2*>(&hH);
    hc[2 * tid]     = __low2float(h2);
    hc[2 * tid + 1] = __high2float(h2);
    __syncthreads();
    const float* w = Whid + (size_t)tid * 512;
    float ssum = bhid[tid];
#pragma unroll 8
    for (int k = 0; k < 512; k++) ssum += hc[k] * w[k];
    outh[(size_t)b * NH + tid] = tanhf(ssum);
}

// ---------------- launcher ---------------------------------------------------
extern "C" void kernel_launch(void* const* d_in, const int* in_sizes, int n_in,
                              void* d_out, int out_size)
{
    const float* src   = (const float*)d_in[0];
    const float* Wih_f = (const float*)d_in[1];
    const float* Whh_f = (const float*)d_in[2];
    const float* bih_f = (const float*)d_in[3];
    const float* bhh_f = (const float*)d_in[4];
    const float* Wih_b = (const float*)d_in[5];
    const float* Whh_b = (const float*)d_in[6];
    const float* bih_b = (const float*)d_in[7];
    const float* bhh_b = (const float*)d_in[8];
    const float* Wout  = (const float*)d_in[9];
    const float* bout  = (const float*)d_in[10];
    const float* Whid  = (const float*)d_in[11];
    const float* bhid  = (const float*)d_in[12];
    float* out = (float*)d_out;

    const int gemm_smem = 2 * 3 * PB * (int)sizeof(unsigned);   // 61440
    cudaFuncSetAttribute(gemm_gx_tc,
                         cudaFuncAttributeMaxDynamicSharedMemorySize, gemm_smem);
    cudaFuncSetAttribute(gemm_proj_tc,
                         cudaFuncAttributeMaxDynamicSharedMemorySize, gemm_smem);
    const int rec_smem = (8 + 4 * SLOT_U32 + 192 * 132) * (int)sizeof(unsigned)
                       + 192 * 9 * (int)sizeof(float) + 64;     // ~126 KB
    cudaFuncSetAttribute(gru_rec_clu,
                         cudaFuncAttributeMaxDynamicSharedMemorySize, rec_smem);

    static cudaStream_t s1 = nullptr, s2 = nullptr;
    static cudaEvent_t evF = nullptr, evJ1 = nullptr, evJ2 = nullptr;
    if (!s1) {
        cudaStreamCreateWithFlags(&s1, cudaStreamNonBlocking);
        cudaStreamCreateWithFlags(&s2, cudaStreamNonBlocking);
        cudaEventCreateWithFlags(&evF,  cudaEventDisableTiming);
        cudaEventCreateWithFlags(&evJ1, cudaEventDisableTiming);
        cudaEventCreateWithFlags(&evJ2, cudaEventDisableTiming);
    }

    init_done_kernel<<<1, 512>>>();
    conv_src_kernel<<<65536, 256>>>(src);
    conv_wih_kernel<<<1536, 256>>>(Wih_f, Wih_b);
    conv_wout_kernel<<<256, 256>>>(Wout);

    cudaEventRecord(evF, 0);
    cudaStreamWaitEvent(s1, evF, 0);
    cudaStreamWaitEvent(s2, evF, 0);

    // rec first (claims its 64 SMs), gx fills the remaining ~84 SMs.
    gru_rec_clu<<<64, 384, rec_smem, s1>>>(Whh_f, bhh_f, Whh_b, bhh_b);
    gemm_gx_tc<<<3072, 256, gemm_smem, s2>>>(bih_f, bih_b);

    cudaEventRecord(evJ1, s1);
    cudaEventRecord(evJ2, s2);
    cudaStreamWaitEvent(0, evJ1, 0);
    cudaStreamWaitEvent(0, evJ2, 0);

    gemm_proj_tc<<<dim3(256, 2), 256, gemm_smem>>>(bout, out);
    hidden_kernel<<<64, 256>>>(Whid, bhid, out + (size_t)NT * NB * NH);
}

// round 17
// speedup vs baseline: 1.6691x; 1.4643x over previous
#include <cuda_runtime.h>
#include <cuda_fp16.h>
#include <math.h>

#define NT 512
#define NB 64
#define NI 1024
#define NH 256
#define NG 768   // 3*NH

// ---------------- scratch (device globals: no allocations allowed) ----------
__device__ float    g_gx_f[NT * NB * NG];     // 100.7 MB
__device__ float    g_gx_b[NT * NB * NG];     // 100.7 MB
__device__ unsigned g_srcH[32768 * 512];      // src fp16-hi k-pairs
__device__ unsigned g_wH[1536 * 512];         // Wih_f|Wih_b fp16 hi
__device__ unsigned g_woH[256 * 256];         // Wout fp16 hi
__device__ unsigned g_woL[256 * 256];         // Wout fp16 lo
__device__ unsigned g_poutH[32768 * 256];     // h history fp16-hi: [t*64+b][fwd|bwd]
__device__ unsigned g_done[2 * 256];          // gx completion counters per (dir, m-block)

__global__ void init_done_kernel() { g_done[threadIdx.x] = 0u; }

// ---------------- helpers ----------------------------------------------------
__device__ __forceinline__ unsigned hpack(float x, float y) {
    __half2 h2 = __floats2half2_rn(x, y);
    return *reinterpret_cast<unsigned*>(&h2);
}
__device__ __forceinline__ void hsplit(float x, float y, unsigned& hi, unsigned& lo) {
    __half2 h2 = __floats2half2_rn(x, y);
    hi = *reinterpret_cast<unsigned*>(&h2);
    float rx = x - __low2float(h2);
    float ry = y - __high2float(h2);
    __half2 l2 = __floats2half2_rn(rx, ry);
    lo = *reinterpret_cast<unsigned*>(&l2);
}

#define MMA_F16(d, a0, a1, a2, a3, b0, b1)                                      \
    asm volatile("mma.sync.aligned.m16n8k16.row.col.f32.f16.f16.f32 "           \
        "{%0,%1,%2,%3}, {%4,%5,%6,%7}, {%8,%9}, {%0,%1,%2,%3};"                 \
        : "+f"(d[0]), "+f"(d[1]), "+f"(d[2]), "+f"(d[3])                        \
        : "r"(a0), "r"(a1), "r"(a2), "r"(a3), "r"(b0), "r"(b1))

#define MMA_F16A(d, a, b0, b1) MMA_F16(d, (a)[0], (a)[1], (a)[2], (a)[3], b0, b1)

__device__ __forceinline__ void cp16(unsigned smem_dst, const void* gsrc) {
    asm volatile("cp.async.cg.shared.global [%0], [%1], 16;"
                 :: "r"(smem_dst), "l"(gsrc));
}
#define CP_COMMIT() asm volatile("cp.async.commit_group;")
#define CP_WAIT(n)  asm volatile("cp.async.wait_group %0;" :: "n"(n))

__device__ __forceinline__ unsigned smem_u32(const void* p) {
    return (unsigned)__cvta_generic_to_shared(p);
}
__device__ __forceinline__ unsigned mapa_u32(unsigned addr, unsigned rank) {
    unsigned r; asm("mapa.shared::cluster.u32 %0, %1, %2;" : "=r"(r) : "r"(addr), "r"(rank));
    return r;
}
__device__ __forceinline__ void st_async_u32(unsigned raddr, unsigned val, unsigned rmbar) {
    asm volatile("st.async.shared::cluster.mbarrier::complete_tx::bytes.b32 [%0], %1, [%2];"
                 :: "r"(raddr), "r"(val), "r"(rmbar) : "memory");
}
__device__ __forceinline__ void mbar_init(unsigned mbar, unsigned cnt) {
    asm volatile("mbarrier.init.shared.b64 [%0], %1;" :: "r"(mbar), "r"(cnt) : "memory");
}
__device__ __forceinline__ void mbar_arrive_expect(unsigned mbar, unsigned bytes) {
    asm volatile("mbarrier.arrive.expect_tx.shared.b64 _, [%0], %1;"
                 :: "r"(mbar), "r"(bytes) : "memory");
}
__device__ __forceinline__ void mbar_wait(unsigned mbar, unsigned ph) {
    asm volatile(
        "{\n\t.reg .pred P;\n"
        "W%=:\n\t"
        "mbarrier.try_wait.parity.acquire.cluster.shared::cta.b64 P, [%0], %1, 0x989680;\n\t"
        "@P bra.uni D%=;\n\t"
        "bra.uni W%=;\n\t"
        "D%=:\n\t}"
        :: "r"(mbar), "r"(ph) : "memory");
}
#define CLUSTER_SYNC() do {                                                     \
    asm volatile("barrier.cluster.arrive.aligned;" ::: "memory");               \
    asm volatile("barrier.cluster.wait.aligned;" ::: "memory");                 \
} while (0)

__device__ __forceinline__ void wait_done(const unsigned* p) {
    unsigned v;
    asm volatile("ld.acquire.gpu.global.u32 %0, [%1];" : "=r"(v) : "l"(p));
    while (v < 6u) {
        __nanosleep(64);
        asm volatile("ld.acquire.gpu.global.u32 %0, [%1];" : "=r"(v) : "l"(p));
    }
}

// COHERENT L2 load (nc path raced with the concurrent producer in R15).
__device__ __forceinline__ float2 ldcg2(const float* p) {
    float2 v;
    asm volatile("ld.global.cg.v2.f32 {%0,%1}, [%2];"
                 : "=f"(v.x), "=f"(v.y) : "l"(p));
    return v;
}

// fast transcendentals (rel err ~1e-6)
__device__ __forceinline__ float ex2a(float x) {
    float y; asm("ex2.approx.ftz.f32 %0, %1;" : "=f"(y) : "f"(x)); return y;
}
__device__ __forceinline__ float rcpa(float x) {
    float y; asm("rcp.approx.ftz.f32 %0, %1;" : "=f"(y) : "f"(x)); return y;
}
__device__ __forceinline__ float fsig(float x) {
    return rcpa(1.f + ex2a(-1.4426950408889634f * x));
}
__device__ __forceinline__ float ftanh(float x) {
    return __fmaf_rn(-2.f, rcpa(1.f + ex2a(2.8853900817779268f * x)), 1.f);
}

// ---------------- conversion kernels (run once per launch) ------------------
__global__ __launch_bounds__(256) void conv_src_kernel(const float* __restrict__ a) {
    const int i = blockIdx.x * 256 + threadIdx.x;
    float2 v = ((const float2*)a)[i];
    g_srcH[i] = hpack(v.x, v.y);
}
__global__ __launch_bounds__(256) void conv_wih_kernel(
    const float* __restrict__ f, const float* __restrict__ b) {
    const int i = blockIdx.x * 256 + threadIdx.x;
    float2 v = ((const float2*)f)[i];
    g_wH[i] = hpack(v.x, v.y);
    float2 w = ((const float2*)b)[i];
    g_wH[768 * 512 + i] = hpack(w.x, w.y);
}
__global__ __launch_bounds__(256) void conv_wout_kernel(const float* __restrict__ a) {
    const int i = blockIdx.x * 256 + threadIdx.x;
    float2 v = ((const float2*)a)[i];
    unsigned h, l; hsplit(v.x, v.y, h, l);
    g_woH[i] = h; g_woL[i] = l;
}

// ---------------- shared mma tile compute (128x128 tile, 8 warps) -----------
#define SST2 20
#define PB (128 * SST2)     // u32 per plane

// 2-term (proj): acc += Ah*Bh + Ah*Bl
__device__ __forceinline__ void mma_tile_f16(
    const unsigned* Ah, const unsigned* Bh, const unsigned* Bl,
    float acc[2][8][4], int wm, int wn, int grp, int tig)
{
#pragma unroll
    for (int kk = 0; kk < 2; kk++) {
        unsigned ah[2][4];
#pragma unroll
        for (int s = 0; s < 2; s++) {
            const int r = wm * 32 + s * 16 + grp;
            const int base = r * SST2 + kk * 8 + tig;
            ah[s][0] = Ah[base];            ah[s][1] = Ah[base + 8 * SST2];
            ah[s][2] = Ah[base + 4];        ah[s][3] = Ah[base + 8 * SST2 + 4];
        }
#pragma unroll
        for (int ns = 0; ns < 8; ns++) {
            const int n = wn * 64 + ns * 8 + grp;
            const int nb = n * SST2 + kk * 8 + tig;
            const unsigned bh0 = Bh[nb], bh1 = Bh[nb + 4];
            const unsigned bl0 = Bl[nb], bl1 = Bl[nb + 4];
#pragma unroll
            for (int s = 0; s < 2; s++) {
                MMA_F16A(acc[s][ns], ah[s], bh0, bh1);
                MMA_F16A(acc[s][ns], ah[s], bl0, bl1);
            }
        }
    }
}

// 1-term (gx): acc += Ah*Bh
__device__ __forceinline__ void mma_tile_f16_1(
    const unsigned* Ah, const unsigned* Bh,
    float acc[2][8][4], int wm, int wn, int grp, int tig)
{
#pragma unroll
    for (int kk = 0; kk < 2; kk++) {
        unsigned ah[2][4];
#pragma unroll
        for (int s = 0; s < 2; s++) {
            const int r = wm * 32 + s * 16 + grp;
            const int base = r * SST2 + kk * 8 + tig;
            ah[s][0] = Ah[base];            ah[s][1] = Ah[base + 8 * SST2];
            ah[s][2] = Ah[base + 4];        ah[s][3] = Ah[base + 8 * SST2 + 4];
        }
#pragma unroll
        for (int ns = 0; ns < 8; ns++) {
            const int n = wn * 64 + ns * 8 + grp;
            const int nb = n * SST2 + kk * 8 + tig;
            const unsigned bh0 = Bh[nb], bh1 = Bh[nb + 4];
#pragma unroll
            for (int s = 0; s < 2; s++)
                MMA_F16A(acc[s][ns], ah[s], bh0, bh1);
        }
    }
}

// ---------------- Kernel 1: gx = src @ Wih^T + bih (1-term fp16) ------------
// Priority-ordered grid; 2-plane staging; release completion signal.
__global__ __launch_bounds__(256, 2) void gemm_gx_tc(
    const float* __restrict__ bih_f, const float* __restrict__ bih_b)
{
    extern __shared__ unsigned sm[];
    const unsigned sbase = smem_u32(sm);

    const int bid = blockIdx.x;
    const int g = bid / 12, i = bid % 12;
    const bool fwd = (i < 6);
    const int mb = fwd ? g : (255 - g);
    const int m0 = mb * 128;
    const int n0 = (fwd ? i : (i - 6)) * 128;
    const float* bias = fwd ? (bih_f + n0) : (bih_b + n0);
    float* outp = fwd ? g_gx_f : g_gx_b;
    const size_t wrow = (size_t)(fwd ? 0 : NG) * 512;

    const int tid = threadIdx.x;
    const int lane = tid & 31, warp = tid >> 5;
    const int wm = warp >> 1, wn = warp & 1;
    const int grp = lane >> 2, tig = lane & 3;
    const int r0 = tid >> 2, c0 = (tid & 3) * 4;

    float acc[2][8][4];
#pragma unroll
    for (int s = 0; s < 2; s++)
#pragma unroll
        for (int ns = 0; ns < 8; ns++)
#pragma unroll
            for (int q = 0; q < 4; q++) acc[s][ns][q] = 0.f;

    auto issue = [&](int kt, int buf) {
        const unsigned b = sbase + (unsigned)buf * 2u * PB * 4u;
#pragma unroll
        for (int l = 0; l < 2; l++) {
            const int row = r0 + l * 64;
            const unsigned d = b + (unsigned)(row * SST2 + c0) * 4u;
            const size_t ga = (size_t)(m0 + row) * 512 + kt * 16 + c0;
            const size_t gb = wrow + (size_t)(n0 + row) * 512 + kt * 16 + c0;
            cp16(d,          g_srcH + ga);
            cp16(d + PB * 4, g_wH + gb);
        }
        CP_COMMIT();
    };

    issue(0, 0);
    issue(1, 1);
    for (int kt = 0; kt < 32; kt++) {
        if (kt == 31) { CP_WAIT(0); } else { CP_WAIT(1); }
        __syncthreads();
        const unsigned* bp = sm + (kt & 1) * 2 * PB;
        mma_tile_f16_1(bp, bp + PB, acc, wm, wn, grp, tig);
        __syncthreads();
        if (kt + 2 < 32) issue(kt + 2, kt & 1);
    }

#pragma unroll
    for (int ns = 0; ns < 8; ns++) {
        const int cl = wn * 64 + ns * 8 + tig * 2;
        const float b0 = bias[cl], b1 = bias[cl + 1];
#pragma unroll
        for (int s = 0; s < 2; s++) {
            const int r = m0 + wm * 32 + s * 16 + grp;
            float* p0 = outp + (size_t)r * NG + n0 + cl;
            float* p1 = outp + (size_t)(r + 8) * NG + n0 + cl;
            *(float2*)p0 = make_float2(acc[s][ns][0] + b0, acc[s][ns][1] + b1);
            *(float2*)p1 = make_float2(acc[s][ns][2] + b0, acc[s][ns][3] + b1);
        }
    }

    __threadfence();
    __syncthreads();
    if (tid == 0) {
        unsigned* cp = &g_done[(fwd ? 0 : 256) + mb];
        asm volatile("red.release.gpu.global.add.u32 [%0], %1;"
                     :: "l"(cp), "r"(1u) : "memory");
    }
}

// ---------------- Kernel 2: clustered GRU recurrence (polls gx progress) ----
#define SLOT_U32 1056                 // 8 batches x 132

__global__ __launch_bounds__(384, 1) __cluster_dims__(4, 1, 1)
void gru_rec_clu(
    const float* __restrict__ Whh_f, const float* __restrict__ bhh_f,
    const float* __restrict__ Whh_b, const float* __restrict__ bhh_b)
{
    extern __shared__ unsigned dsm[];
    unsigned* mbar = dsm;                      // 4 x u64
    unsigned* hsH  = dsm + 8;                  // [4][8][132]
    unsigned* wlo  = hsH + 4 * SLOT_U32;       // [192][132]
    float*    red  = (float*)(wlo + 192 * 132);// [192][9]

    const int cta = blockIdx.x;
    const int tid = threadIdx.x;
    const int dir = cta >> 5;
    const int c5  = cta & 31;
    const int group = c5 >> 2;
    const int rank  = c5 & 3;
    const float* Whh = dir ? Whh_b : Whh_f;
    const float* bhh = dir ? bhh_b : bhh_f;
    const float* gx  = dir ? g_gx_b : g_gx_f;
    const unsigned* done = g_done + dir * 256;

    const int lane = tid & 31, w = tid >> 5;   // 12 warps
    const int grp = lane >> 2, tig = lane & 3;
    const int lr0 = 16 * w + grp, lr1 = lr0 + 8;

    unsigned waH[16][4];
    {
        const int g0 = lr0 >> 6, g1 = lr1 >> 6;
        const float* row0 = Whh + (size_t)(g0 * NH + 64 * rank + (lr0 & 63)) * NH;
        const float* row1 = Whh + (size_t)(g1 * NH + 64 * rank + (lr1 & 63)) * NH;
#pragma unroll
        for (int ks = 0; ks < 16; ks++) {
            const int kp0 = ks * 8 + tig, kp1 = kp0 + 4;
            unsigned h, l;
            float2 v;
            v = *(const float2*)(row0 + 2 * kp0); hsplit(v.x, v.y, h, l);
            waH[ks][0] = h; wlo[lr0 * 132 + kp0] = l;
            v = *(const float2*)(row1 + 2 * kp0); hsplit(v.x, v.y, h, l);
            waH[ks][1] = h; wlo[lr1 * 132 + kp0] = l;
            v = *(const float2*)(row0 + 2 * kp1); hsplit(v.x, v.y, h, l);
            waH[ks][2] = h; wlo[lr0 * 132 + kp1] = l;
            v = *(const float2*)(row1 + 2 * kp1); hsplit(v.x, v.y, h, l);
            waH[ks][3] = h; wlo[lr1 * 132 + kp1] = l;
        }
    }

    const int bl = tid >> 5;
    const int jp = lane;
    const int bglob = group * 8 + bl;
    const int jg0 = 64 * rank + 2 * jp;
    float br0 = 0.f, br1 = 0.f, bz0 = 0.f, bz1 = 0.f, bn0 = 0.f, bn1 = 0.f;
    if (tid < 256) {
        br0 = bhh[jg0];       br1 = bhh[jg0 + 1];
        bz0 = bhh[256 + jg0]; bz1 = bhh[256 + jg0 + 1];
        bn0 = bhh[512 + jg0]; bn1 = bhh[512 + jg0 + 1];
    }
    float hp0 = 0.f, hp1 = 0.f;

    for (int i = tid; i < 4 * SLOT_U32; i += 384) hsH[i] = 0u;
    const unsigned mbar_b = smem_u32(mbar);
    if (tid == 0) {
#pragma unroll
        for (int q = 0; q < 4; q++) mbar_init(mbar_b + q * 8, 1);
    }
    __syncthreads();
    CLUSTER_SYNC();

    const unsigned hsH_b = smem_u32(hsH);
    unsigned rH[4], rM[4];
#pragma unroll
    for (int rk = 0; rk < 4; rk++) {
        rH[rk] = mapa_u32(hsH_b, rk);
        rM[rk] = mapa_u32(mbar_b, rk);
    }

    float pxr0, pxr1, pxz0, pxz1, pxn0, pxn1;
    if (tid < 256) {
        const int t0 = dir ? (NT - 1) : 0;
        wait_done(done + (t0 >> 1));
        const float* gp = gx + ((size_t)t0 * NB + bglob) * NG + jg0;
        float2 a = ldcg2(gp);
        float2 b = ldcg2(gp + 256);
        float2 c = ldcg2(gp + 512);
        pxr0 = a.x; pxr1 = a.y; pxz0 = b.x; pxz1 = b.y; pxn0 = c.x; pxn1 = c.y;
    }

    unsigned phases = 0;

    for (int s = 0; s < NT; s++) {
        const int rs = s & 3;
        const int ws = (s + 1) & 3;
        const int rb = rs * SLOT_U32;

        if (tid == 0 && s + 1 < NT)
            mbar_arrive_expect(mbar_b + ws * 8, 4096);
        if (s > 0) {
            mbar_wait(mbar_b + rs * 8, (phases >> rs) & 1);
            phases ^= (1u << rs);
        }

        float nxr0 = 0.f, nxr1 = 0.f, nxz0 = 0.f, nxz1 = 0.f, nxn0 = 0.f, nxn1 = 0.f;
        if (tid < 256 && s + 1 < NT) {
            const int tn = dir ? (NT - 2 - s) : (s + 1);
            wait_done(done + (tn >> 1));
            const float* gp = gx + ((size_t)tn * NB + bglob) * NG + jg0;
            float2 a = ldcg2(gp);
            float2 b = ldcg2(gp + 256);
            float2 c = ldcg2(gp + 512);
            nxr0 = a.x; nxr1 = a.y; nxz0 = b.x; nxz1 = b.y; nxn0 = c.x; nxn1 = c.y;
        }

        float aA[4] = {0.f, 0.f, 0.f, 0.f};
        float aB[4] = {0.f, 0.f, 0.f, 0.f};
#pragma unroll
        for (int ks = 0; ks < 16; ks++) {
            const int kp = ks * 8 + tig;
            const unsigned bh0 = hsH[rb + grp * 132 + kp];
            const unsigned bh1 = hsH[rb + grp * 132 + kp + 4];
            const unsigned al0 = wlo[lr0 * 132 + kp];
            const unsigned al1 = wlo[lr1 * 132 + kp];
            const unsigned al2 = wlo[lr0 * 132 + kp + 4];
            const unsigned al3 = wlo[lr1 * 132 + kp + 4];
            MMA_F16A(aA, waH[ks], bh0, bh1);
            MMA_F16(aB, al0, al1, al2, al3, bh0, bh1);
        }
        red[lr0 * 9 + tig * 2]     = aA[0] + aB[0];
        red[lr0 * 9 + tig * 2 + 1] = aA[1] + aB[1];
        red[lr1 * 9 + tig * 2]     = aA[2] + aB[2];
        red[lr1 * 9 + tig * 2 + 1] = aA[3] + aB[3];
        __syncthreads();

        if (tid < 256) {
            const int j0 = 2 * jp, j1 = j0 + 1;
            const float ghr0 = red[j0 * 9 + bl],         ghr1 = red[j1 * 9 + bl];
            const float ghz0 = red[(64 + j0) * 9 + bl],  ghz1 = red[(64 + j1) * 9 + bl];
            const float ghn0 = red[(128 + j0) * 9 + bl], ghn1 = red[(128 + j1) * 9 + bl];

            const float r0 = fsig(pxr0 + ghr0 + br0);
            const float z0 = fsig(pxz0 + ghz0 + bz0);
            const float n0 = ftanh(pxn0 + r0 * (ghn0 + bn0));
            const float h0 = (1.f - z0) * n0 + z0 * hp0;
            const float r1 = fsig(pxr1 + ghr1 + br1);
            const float z1 = fsig(pxz1 + ghz1 + bz1);
            const float n1 = ftanh(pxn1 + r1 * (ghn1 + bn1));
            const float h1 = (1.f - z1) * n1 + z1 * hp1;
            hp0 = h0; hp1 = h1;

            const unsigned hi = hpack(h0, h1);
            const int t = dir ? (NT - 1 - s) : s;
            const int col = rank * 32 + jp;
            if (s + 1 < NT) {
                const unsigned offH = (unsigned)(ws * SLOT_U32 + bl * 132 + col) * 4u;
                const unsigned mb_off = (unsigned)(ws * 8);
#pragma unroll
                for (int rk = 0; rk < 4; rk++)
                    st_async_u32(rH[rk] + offH, hi, rM[rk] + mb_off);
            }
            g_poutH[((size_t)t * NB + bglob) * 256 + dir * 128 + col] = hi;

            pxr0 = nxr0; pxr1 = nxr1; pxz0 = nxz0; pxz1 = nxz1; pxn0 = nxn0; pxn1 = nxn1;
        }
    }
}

// ---------------- Kernel 3: outputs = h_hist @ Wout^T + bout (2-term) -------
__global__ __launch_bounds__(256, 2) void gemm_proj_tc(
    const float* __restrict__ bout, float* __restrict__ dst)
{
    extern __shared__ unsigned sm[];
    const unsigned sbase = smem_u32(sm);

    const int m0 = blockIdx.x * 128;
    const int n0 = blockIdx.y * 128;
    const int tid = threadIdx.x;
    const int lane = tid & 31, warp = tid >> 5;
    const int wm = warp >> 1, wn = warp & 1;
    const int grp = lane >> 2, tig = lane & 3;
    const int r0 = tid >> 2, c0 = (tid & 3) * 4;

    float acc[2][8][4];
#pragma unroll
    for (int s = 0; s < 2; s++)
#pragma unroll
        for (int ns = 0; ns < 8; ns++)
#pragma unroll
            for (int q = 0; q < 4; q++) acc[s][ns][q] = 0.f;

    auto issue = [&](int kt, int buf) {
        const unsigned b = sbase + (unsigned)buf * 3u * PB * 4u;
#pragma unroll
        for (int l = 0; l < 2; l++) {
            const int row = r0 + l * 64;
            const unsigned d = b + (unsigned)(row * SST2 + c0) * 4u;
            const size_t ga = (size_t)(m0 + row) * 256 + kt * 16 + c0;
            const size_t gb = (size_t)(n0 + row) * 256 + kt * 16 + c0;
            cp16(d,              g_poutH + ga);
            cp16(d + PB * 4,     g_woH + gb);
            cp16(d + 2 * PB * 4, g_woL + gb);
        }
        CP_COMMIT();
    };

    issue(0, 0);
    issue(1, 1);
    for (int kt = 0; kt < 16; kt++) {
        if (kt == 15) { CP_WAIT(0); } else { CP_WAIT(1); }
        __syncthreads();
        const unsigned* bp = sm + (kt & 1) * 3 * PB;
        mma_tile_f16(bp, bp + PB, bp + 2 * PB, acc, wm, wn, grp, tig);
        __syncthreads();
        if (kt + 2 < 16) issue(kt + 2, kt & 1);
    }

#pragma unroll
    for (int ns = 0; ns < 8; ns++) {
        const int cl = wn * 64 + ns * 8 + tig * 2;
        const float b0 = bout[n0 + cl], b1 = bout[n0 + cl + 1];
#pragma unroll
        for (int s = 0; s < 2; s++) {
            const int r = m0 + wm * 32 + s * 16 + grp;
            float* p0 = dst + (size_t)r * NH + n0 + cl;
            float* p1 = dst + (size_t)(r + 8) * NH + n0 + cl;
            *(float2*)p0 = make_float2(acc[s][ns][0] + b0, acc[s][ns][1] + b1);
            *(float2*)p1 = make_float2(acc[s][ns][2] + b0, acc[s][ns][3] + b1);
        }
    }
}

// ---------------- Kernel 4: hidden = tanh([h_f|h_b] @ Whid^T + bhid) --------
__global__ __launch_bounds__(256) void hidden_kernel(
    const float* __restrict__ Whid, const float* __restrict__ bhid,
    float* __restrict__ outh)
{
    __shared__ float hc[512];
    const int b = blockIdx.x, tid = threadIdx.x;
    const size_t row = (tid < 128) ? ((size_t)(NT - 1) * NB + b) : (size_t)b;
    const unsigned hH = g_poutH[row * 256 + tid];
    __half2 h2 = *reinterpret_cast<const __half2*>(&hH);
    hc[2 * tid]     = __low2float(h2);
    hc[2 * tid + 1] = __high2float(h2);
    __syncthreads();
    const float* w = Whid + (size_t)tid * 512;
    float ssum = bhid[tid];
#pragma unroll 8
    for (int k = 0; k < 512; k++) ssum += hc[k] * w[k];
    outh[(size_t)b * NH + tid] = tanhf(ssum);
}

// ---------------- launcher ---------------------------------------------------
extern "C" void kernel_launch(void* const* d_in, const int* in_sizes, int n_in,
                              void* d_out, int out_size)
{
    const float* src   = (const float*)d_in[0];
    const float* Wih_f = (const float*)d_in[1];
    const float* Whh_f = (const float*)d_in[2];
    const float* bih_f = (const float*)d_in[3];
    const float* bhh_f = (const float*)d_in[4];
    const float* Wih_b = (const float*)d_in[5];
    const float* Whh_b = (const float*)d_in[6];
    const float* bih_b = (const float*)d_in[7];
    const float* bhh_b = (const float*)d_in[8];
    const float* Wout  = (const float*)d_in[9];
    const float* bout  = (const float*)d_in[10];
    const float* Whid  = (const float*)d_in[11];
    const float* bhid  = (const float*)d_in[12];
    float* out = (float*)d_out;

    const int gx_smem = 2 * 2 * PB * (int)sizeof(unsigned);     // 40960
    cudaFuncSetAttribute(gemm_gx_tc,
                         cudaFuncAttributeMaxDynamicSharedMemorySize, gx_smem);
    const int proj_smem = 2 * 3 * PB * (int)sizeof(unsigned);   // 61440
    cudaFuncSetAttribute(gemm_proj_tc,
                         cudaFuncAttributeMaxDynamicSharedMemorySize, proj_smem);
    const int rec_smem = (8 + 4 * SLOT_U32 + 192 * 132) * (int)sizeof(unsigned)
                       + 192 * 9 * (int)sizeof(float) + 64;     // ~126 KB
    cudaFuncSetAttribute(gru_rec_clu,
                         cudaFuncAttributeMaxDynamicSharedMemorySize, rec_smem);

    static cudaStream_t s1 = nullptr, s2 = nullptr;
    static cudaEvent_t evF = nullptr, evJ1 = nullptr, evJ2 = nullptr;
    if (!s1) {
        cudaStreamCreateWithFlags(&s1, cudaStreamNonBlocking);
        cudaStreamCreateWithFlags(&s2, cudaStreamNonBlocking);
        cudaEventCreateWithFlags(&evF,  cudaEventDisableTiming);
        cudaEventCreateWithFlags(&evJ1, cudaEventDisableTiming);
        cudaEventCreateWithFlags(&evJ2, cudaEventDisableTiming);
    }

    init_done_kernel<<<1, 512>>>();
    conv_src_kernel<<<65536, 256>>>(src);
    conv_wih_kernel<<<1536, 256>>>(Wih_f, Wih_b);
    conv_wout_kernel<<<256, 256>>>(Wout);

    cudaEventRecord(evF, 0);
    cudaStreamWaitEvent(s1, evF, 0);
    cudaStreamWaitEvent(s2, evF, 0);

    gru_rec_clu<<<64, 384, rec_smem, s1>>>(Whh_f, bhh_f, Whh_b, bhh_b);
    gemm_gx_tc<<<3072, 256, gx_smem, s2>>>(bih_f, bih_b);

    cudaEventRecord(evJ1, s1);
    cudaEventRecord(evJ2, s2);
    cudaStreamWaitEvent(0, evJ1, 0);
    cudaStreamWaitEvent(0, evJ2, 0);

    gemm_proj_tc<<<dim3(256, 2), 256, proj_smem>>>(bout, out);
    hidden_kernel<<<64, 256>>>(Whid, bhid, out + (size_t)NT * NB * NH);
}